// round 12
// baseline (speedup 1.0000x reference)
#include <cuda_runtime.h>
#include <cuda_bf16.h>

// Problem constants
#define T_STEPS 1000
#define T_MAIN  990            // readout tail covers [990, 1000)
#define BATCH   256
#define HID     512
#define NIN     3
#define NOUT    2
#define BH      (BATCH * HID)             // 131072
#define SPK_ELEMS ((size_t)T_STEPS * BH)  // 131,072,000

#define BETA    0.8f
#define THRESH  1.0f

// 256-bit streaming store (Blackwell sm_100+): one STG.256 per thread per t.
__device__ __forceinline__ void stg256_cs(float* p,
                                          float a0, float a1, float a2, float a3,
                                          float a4, float a5, float a6, float a7)
{
    asm volatile("st.global.cs.v8.f32 [%0], {%1,%2,%3,%4,%5,%6,%7,%8};"
                 :: "l"(p), "f"(a0), "f"(a1), "f"(a2), "f"(a3),
                    "f"(a4), "f"(a5), "f"(a6), "f"(a7)
                 : "memory");
}

// ---------------------------------------------------------------------------
// Fused kernel, 256-bit store variant.
// Grid: 256 blocks (one per b). 64 threads; thread owns 8 consecutive hidden
// units h = tid*8..tid*8+7 (32B-aligned -> STG.256 spike store per t; the
// block still writes one contiguous 2KB slice per timestep, in half the
// transactions). x[:, b, :] staged in shared, float4-padded rows -> one
// broadcast LDS.128 per step. Readout tail fused as before.
// ---------------------------------------------------------------------------
__global__ __launch_bounds__(64)
void snn_fused_kernel(const float* __restrict__ x,     // [T, B, 3]
                      const float* __restrict__ W1,    // [512, 3]
                      const float* __restrict__ W2,    // [2, 512]
                      float* __restrict__ spk_out,     // [T, B, 512]
                      float* __restrict__ avg_out)     // [B, 2]
{
    __shared__ float sx[T_STEPS * 4];   // 16 KB, x rows padded 3 -> 4
    __shared__ float red[2][20];
    __shared__ float tot[20];

    const int b    = blockIdx.x;
    const int tid  = threadIdx.x;
    const int lane = tid & 31;
    const int wid  = tid >> 5;          // 0..1
    const int h0   = tid * 8;

    // Stage x[:, b, :] into shared (3000 scalar loads over 64 threads)
    for (int idx = tid; idx < T_STEPS * NIN; idx += 64) {
        const int t = idx / 3;
        const int i = idx - t * 3;
        sx[t * 4 + i] = x[(size_t)t * (BATCH * NIN) + b * NIN + i];
    }
    __syncthreads();

    // W1 rows for the 8 owned hidden units: 24 contiguous floats (6 float4)
    float w[8][3];
    {
        const float4* W1v = reinterpret_cast<const float4*>(W1 + h0 * 3);
        float wf[24];
        #pragma unroll
        for (int q = 0; q < 6; ++q) {
            const float4 v = W1v[q];
            wf[q * 4 + 0] = v.x; wf[q * 4 + 1] = v.y;
            wf[q * 4 + 2] = v.z; wf[q * 4 + 3] = v.w;
        }
        #pragma unroll
        for (int j = 0; j < 8; ++j) {
            w[j][0] = wf[j * 3 + 0];
            w[j][1] = wf[j * 3 + 1];
            w[j][2] = wf[j * 3 + 2];
        }
    }

    const float4* __restrict__ sx4 = reinterpret_cast<const float4*>(sx);
    float* __restrict__ out = spk_out + (size_t)b * HID + h0;

    float m[8];
    #pragma unroll
    for (int j = 0; j < 8; ++j) m[j] = 0.0f;

    // ---- main scan: t in [0, 990) ----
    #pragma unroll 2
    for (int t = 0; t < T_MAIN; ++t) {
        const float4 xv = sx4[t];
        float sp[8];
        #pragma unroll
        for (int j = 0; j < 8; ++j) {
            const float c = fmaf(xv.z, w[j][2], fmaf(xv.y, w[j][1], xv.x * w[j][0]));
            // exact reference: mem_new = (beta*mem + cur) * (1 - (mem_prev > 1))
            m[j] = (m[j] > THRESH) ? 0.0f : fmaf(BETA, m[j], c);
            sp[j] = (m[j] > THRESH) ? 1.0f : 0.0f;
        }
        stg256_cs(out + (size_t)t * BH,
                  sp[0], sp[1], sp[2], sp[3], sp[4], sp[5], sp[6], sp[7]);
    }

    // ---- tail: t in [990, 1000): store spikes + accumulate readout ----
    const float4 w2o0a = reinterpret_cast<const float4*>(W2 + h0)[0];
    const float4 w2o0b = reinterpret_cast<const float4*>(W2 + h0)[1];
    const float4 w2o1a = reinterpret_cast<const float4*>(W2 + HID + h0)[0];
    const float4 w2o1b = reinterpret_cast<const float4*>(W2 + HID + h0)[1];
    const float w2r0[8] = {w2o0a.x, w2o0a.y, w2o0a.z, w2o0a.w,
                           w2o0b.x, w2o0b.y, w2o0b.z, w2o0b.w};
    const float w2r1[8] = {w2o1a.x, w2o1a.y, w2o1a.z, w2o1a.w,
                           w2o1b.x, w2o1b.y, w2o1b.z, w2o1b.w};
    float acc[20];

    #pragma unroll
    for (int k = 0; k < 10; ++k) {
        const int t = T_MAIN + k;
        const float4 xv = sx4[t];
        float sp[8];
        #pragma unroll
        for (int j = 0; j < 8; ++j) {
            const float c = fmaf(xv.z, w[j][2], fmaf(xv.y, w[j][1], xv.x * w[j][0]));
            m[j] = (m[j] > THRESH) ? 0.0f : fmaf(BETA, m[j], c);
            sp[j] = (m[j] > THRESH) ? 1.0f : 0.0f;
        }
        stg256_cs(out + (size_t)t * BH,
                  sp[0], sp[1], sp[2], sp[3], sp[4], sp[5], sp[6], sp[7]);

        float q0 = 0.0f, q1 = 0.0f;
        #pragma unroll
        for (int j = 0; j < 8; ++j) {
            q0 = fmaf(sp[j], w2r0[j], q0);
            q1 = fmaf(sp[j], w2r1[j], q1);
        }
        acc[2 * k + 0] = q0;
        acc[2 * k + 1] = q1;
    }

    // ---- block reduction of the 20 partials (2 warps) ----
    #pragma unroll
    for (int j = 0; j < 20; ++j) {
        #pragma unroll
        for (int off = 16; off > 0; off >>= 1)
            acc[j] += __shfl_xor_sync(0xFFFFFFFFu, acc[j], off);
    }
    if (lane == 0) {
        #pragma unroll
        for (int j = 0; j < 20; ++j) red[wid][j] = acc[j];
    }
    __syncthreads();

    if (tid < 20)
        tot[tid] = red[0][tid] + red[1][tid];
    __syncthreads();

    if (tid < NOUT) {
        float s = 0.0f;
        #pragma unroll
        for (int k = 0; k < 10; ++k) {
            const float z = tot[2 * k + tid];
            s += 1.0f / (1.0f + expf(-z));
        }
        avg_out[b * NOUT + tid] = s * 0.1f;
    }
}

// ---------------------------------------------------------------------------
extern "C" void kernel_launch(void* const* d_in, const int* in_sizes, int n_in,
                              void* d_out, int out_size)
{
    const float* x  = (const float*)d_in[0];   // [1000, 256, 3]
    const float* W1 = (const float*)d_in[1];   // [512, 3]
    const float* W2 = (const float*)d_in[2];   // [2, 512]
    float* out = (float*)d_out;

    float* spk_out = out;                      // 131,072,000 floats
    float* avg_out = out + SPK_ELEMS;          // 512 floats

    snn_fused_kernel<<<BATCH, 64>>>(x, W1, W2, spk_out, avg_out);
}

// round 14
// speedup vs baseline: 1.0546x; 1.0546x over previous
#include <cuda_runtime.h>
#include <cuda_bf16.h>
#include <cstdint>

// Problem constants
#define T_STEPS 1000
#define T_MAIN  990            // readout tail covers [990, 1000)
#define BATCH   256
#define HID     512
#define NIN     3
#define NOUT    2
#define BH      (BATCH * HID)             // 131072
#define SPK_ELEMS ((size_t)T_STEPS * BH)  // 131,072,000

#define BETA    0.8f
#define THRESH  1.0f

#define CHUNK   10             // timesteps per staging chunk; 990 = 99 * 10

__device__ __forceinline__ uint32_t smem_u32(const void* p) {
    return static_cast<uint32_t>(__cvta_generic_to_shared(p));
}

// ---------------------------------------------------------------------------
// Fused kernel, TMA-drained stores.
// Grid: 256 blocks (one per b). 128 threads; thread owns h = tid*4..tid*4+3.
// Main loop computes CHUNK=10 steps of spikes into a smem staging buffer
// (STS.128), then thread 0 drains the 10 contiguous 2KB t-slices to global
// via cp.async.bulk (TMA engine). Double-buffered: compute of chunk k+1
// overlaps the drain of chunk k. x[:, b, :] staged in shared as before.
// Tail [990,1000) stores via STG and feeds the fused readout.
// ---------------------------------------------------------------------------
__global__ __launch_bounds__(128)
void snn_fused_kernel(const float* __restrict__ x,     // [T, B, 3]
                      const float* __restrict__ W1,    // [512, 3]
                      const float* __restrict__ W2,    // [2, 512]
                      float* __restrict__ spk_out,     // [T, B, 512]
                      float* __restrict__ avg_out)     // [B, 2]
{
    __shared__ float sx[T_STEPS * 4];               // 16 KB
    __shared__ __align__(16) float sbuf[2][CHUNK][HID];  // 2 x 20 KB staging
    __shared__ float red[4][20];
    __shared__ float tot[20];

    const int b    = blockIdx.x;
    const int tid  = threadIdx.x;
    const int lane = tid & 31;
    const int wid  = tid >> 5;
    const int h0   = tid * 4;

    // Stage x[:, b, :] into shared (3000 scalar loads over 128 threads)
    for (int idx = tid; idx < T_STEPS * NIN; idx += 128) {
        const int t = idx / 3;
        const int i = idx - t * 3;
        sx[t * 4 + i] = x[(size_t)t * (BATCH * NIN) + b * NIN + i];
    }
    __syncthreads();

    // W1 rows for the 4 owned hidden units: 12 contiguous floats, 16B aligned
    const float4 w1a = reinterpret_cast<const float4*>(W1 + h0 * 3)[0];
    const float4 w1b = reinterpret_cast<const float4*>(W1 + h0 * 3)[1];
    const float4 w1c = reinterpret_cast<const float4*>(W1 + h0 * 3)[2];
    const float wA0 = w1a.x, wA1 = w1a.y, wA2 = w1a.z;
    const float wB0 = w1a.w, wB1 = w1b.x, wB2 = w1b.y;
    const float wC0 = w1b.z, wC1 = w1b.w, wC2 = w1c.x;
    const float wD0 = w1c.y, wD1 = w1c.z, wD2 = w1c.w;

    const float4* __restrict__ sx4 = reinterpret_cast<const float4*>(sx);
    float* __restrict__ gbase = spk_out + (size_t)b * HID;   // + t*BH per slice

    float m0 = 0.0f, m1 = 0.0f, m2 = 0.0f, m3 = 0.0f;

    // ---- main scan: 99 chunks of 10 timesteps ----
    for (int c = 0; c < T_MAIN / CHUNK; ++c) {
        const int buf = c & 1;

        // Before overwriting this buffer, ensure its previous drain (group
        // c-2) has finished reading. Thread 0 tracks bulk groups; barrier
        // publishes the guarantee to the block.
        if (c >= 2 && tid == 0)
            asm volatile("cp.async.bulk.wait_group.read 1;" ::: "memory");
        __syncthreads();

        float4* __restrict__ srow = reinterpret_cast<float4*>(&sbuf[buf][0][h0]);
        #pragma unroll
        for (int u = 0; u < CHUNK; ++u) {
            const float4 xv = sx4[c * CHUNK + u];
            const float c0 = fmaf(xv.z, wA2, fmaf(xv.y, wA1, xv.x * wA0));
            const float c1 = fmaf(xv.z, wB2, fmaf(xv.y, wB1, xv.x * wB0));
            const float c2 = fmaf(xv.z, wC2, fmaf(xv.y, wC1, xv.x * wC0));
            const float c3 = fmaf(xv.z, wD2, fmaf(xv.y, wD1, xv.x * wD0));
            // exact reference: mem_new = (beta*mem + cur) * (1 - (mem_prev > 1))
            m0 = (m0 > THRESH) ? 0.0f : fmaf(BETA, m0, c0);
            m1 = (m1 > THRESH) ? 0.0f : fmaf(BETA, m1, c1);
            m2 = (m2 > THRESH) ? 0.0f : fmaf(BETA, m2, c2);
            m3 = (m3 > THRESH) ? 0.0f : fmaf(BETA, m3, c3);
            float4 sp;
            sp.x = (m0 > THRESH) ? 1.0f : 0.0f;
            sp.y = (m1 > THRESH) ? 1.0f : 0.0f;
            sp.z = (m2 > THRESH) ? 1.0f : 0.0f;
            sp.w = (m3 > THRESH) ? 1.0f : 0.0f;
            srow[u * (HID / 4)] = sp;          // STS.128, conflict-free
        }
        __syncthreads();   // all spikes of this chunk visible in smem

        if (tid == 0) {
            // order generic-proxy STS before async-proxy bulk reads
            asm volatile("fence.proxy.async.shared::cta;" ::: "memory");
            #pragma unroll
            for (int u = 0; u < CHUNK; ++u) {
                float* gdst = gbase + (size_t)(c * CHUNK + u) * BH;
                const uint32_t ssrc = smem_u32(&sbuf[buf][u][0]);
                asm volatile(
                    "cp.async.bulk.global.shared::cta.bulk_group [%0], [%1], %2;"
                    :: "l"(gdst), "r"(ssrc), "r"(HID * 4) : "memory");
            }
            asm volatile("cp.async.bulk.commit_group;" ::: "memory");
        }
    }

    // ---- tail: t in [990, 1000), STG stores + readout partials ----
    const float4 w2o0 = reinterpret_cast<const float4*>(W2 + h0)[0];
    const float4 w2o1 = reinterpret_cast<const float4*>(W2 + HID + h0)[0];
    float4* __restrict__ out4 = reinterpret_cast<float4*>(gbase + h0);
    float acc[20];

    #pragma unroll
    for (int k = 0; k < 10; ++k) {
        const int t = T_MAIN + k;
        const float4 xv = sx4[t];
        const float c0 = fmaf(xv.z, wA2, fmaf(xv.y, wA1, xv.x * wA0));
        const float c1 = fmaf(xv.z, wB2, fmaf(xv.y, wB1, xv.x * wB0));
        const float c2 = fmaf(xv.z, wC2, fmaf(xv.y, wC1, xv.x * wC0));
        const float c3 = fmaf(xv.z, wD2, fmaf(xv.y, wD1, xv.x * wD0));
        m0 = (m0 > THRESH) ? 0.0f : fmaf(BETA, m0, c0);
        m1 = (m1 > THRESH) ? 0.0f : fmaf(BETA, m1, c1);
        m2 = (m2 > THRESH) ? 0.0f : fmaf(BETA, m2, c2);
        m3 = (m3 > THRESH) ? 0.0f : fmaf(BETA, m3, c3);
        float4 sp;
        sp.x = (m0 > THRESH) ? 1.0f : 0.0f;
        sp.y = (m1 > THRESH) ? 1.0f : 0.0f;
        sp.z = (m2 > THRESH) ? 1.0f : 0.0f;
        sp.w = (m3 > THRESH) ? 1.0f : 0.0f;
        __stcs(out4 + (size_t)t * (BH / 4), sp);

        float q0 = sp.x * w2o0.x; q0 = fmaf(sp.y, w2o0.y, q0);
        q0 = fmaf(sp.z, w2o0.z, q0); q0 = fmaf(sp.w, w2o0.w, q0);
        float q1 = sp.x * w2o1.x; q1 = fmaf(sp.y, w2o1.y, q1);
        q1 = fmaf(sp.z, w2o1.z, q1); q1 = fmaf(sp.w, w2o1.w, q1);
        acc[2 * k + 0] = q0;
        acc[2 * k + 1] = q1;
    }

    // ---- block reduction of the 20 partials ----
    #pragma unroll
    for (int j = 0; j < 20; ++j) {
        #pragma unroll
        for (int off = 16; off > 0; off >>= 1)
            acc[j] += __shfl_xor_sync(0xFFFFFFFFu, acc[j], off);
    }
    if (lane == 0) {
        #pragma unroll
        for (int j = 0; j < 20; ++j) red[wid][j] = acc[j];
    }
    __syncthreads();

    if (tid < 20)
        tot[tid] = red[0][tid] + red[1][tid] + red[2][tid] + red[3][tid];
    __syncthreads();

    if (tid < NOUT) {
        float s = 0.0f;
        #pragma unroll
        for (int k = 0; k < 10; ++k) {
            const float z = tot[2 * k + tid];
            s += 1.0f / (1.0f + expf(-z));
        }
        avg_out[b * NOUT + tid] = s * 0.1f;
    }

    // Drain all outstanding bulk groups before exit.
    if (tid == 0)
        asm volatile("cp.async.bulk.wait_group.read 0;" ::: "memory");
}

// ---------------------------------------------------------------------------
extern "C" void kernel_launch(void* const* d_in, const int* in_sizes, int n_in,
                              void* d_out, int out_size)
{
    const float* x  = (const float*)d_in[0];   // [1000, 256, 3]
    const float* W1 = (const float*)d_in[1];   // [512, 3]
    const float* W2 = (const float*)d_in[2];   // [2, 512]
    float* out = (float*)d_out;

    float* spk_out = out;                      // 131,072,000 floats
    float* avg_out = out + SPK_ELEMS;          // 512 floats

    snn_fused_kernel<<<BATCH, 128>>>(x, W1, W2, spk_out, avg_out);
}

// round 15
// speedup vs baseline: 1.0683x; 1.0130x over previous
#include <cuda_runtime.h>
#include <cuda_bf16.h>

// Problem constants
#define T_STEPS 1000
#define T_MAIN  990            // readout tail covers [990, 1000)
#define BATCH   256
#define HID     512
#define NIN     3
#define NOUT    2
#define BH      (BATCH * HID)             // 131072
#define SPK_ELEMS ((size_t)T_STEPS * BH)  // 131,072,000

#define BETA    0.8f
#define THRESH  1.0f

// ---------------------------------------------------------------------------
// Final converged kernel (champion structure).
// Structurally bound: 524 MB of mandatory f32 spike output at the measured
// ~5.9 TB/s write ceiling => ~88 us floor (verified path-independent:
// STG.128, STG.256, and TMA bulk all hit the same DRAM ceiling).
//
// Grid: 256 blocks (one per batch element b). 128 threads; each thread owns
// 4 consecutive hidden units h = tid*4..tid*4+3 -> one STG.128 streaming
// spike store per timestep (block writes a contiguous 2KB slice per t).
// x[:, b, :] staged in shared, padded to float4 rows -> one broadcast
// LDS.128 per step on the smem pipe, keeping L1tex free for stores.
// Readout over the last 10 steps fused: register partials + block reduce.
// ---------------------------------------------------------------------------
__global__ __launch_bounds__(128)
void snn_fused_kernel(const float* __restrict__ x,     // [T, B, 3]
                      const float* __restrict__ W1,    // [512, 3]
                      const float* __restrict__ W2,    // [2, 512]
                      float* __restrict__ spk_out,     // [T, B, 512]
                      float* __restrict__ avg_out)     // [B, 2]
{
    __shared__ float sx[T_STEPS * 4];   // 16 KB, x rows padded 3 -> 4
    __shared__ float red[4][20];
    __shared__ float tot[20];

    const int b    = blockIdx.x;
    const int tid  = threadIdx.x;
    const int lane = tid & 31;
    const int wid  = tid >> 5;
    const int h0   = tid * 4;

    // Stage x[:, b, :] into shared (3000 scalar loads over 128 threads)
    for (int idx = tid; idx < T_STEPS * NIN; idx += 128) {
        const int t = idx / 3;
        const int i = idx - t * 3;
        sx[t * 4 + i] = x[(size_t)t * (BATCH * NIN) + b * NIN + i];
    }
    __syncthreads();

    // W1 rows for the 4 owned hidden units: 12 contiguous floats, 16B aligned
    const float4 w1a = reinterpret_cast<const float4*>(W1 + h0 * 3)[0];
    const float4 w1b = reinterpret_cast<const float4*>(W1 + h0 * 3)[1];
    const float4 w1c = reinterpret_cast<const float4*>(W1 + h0 * 3)[2];
    const float wA0 = w1a.x, wA1 = w1a.y, wA2 = w1a.z;
    const float wB0 = w1a.w, wB1 = w1b.x, wB2 = w1b.y;
    const float wC0 = w1b.z, wC1 = w1b.w, wC2 = w1c.x;
    const float wD0 = w1c.y, wD1 = w1c.z, wD2 = w1c.w;

    const float4* __restrict__ sx4 = reinterpret_cast<const float4*>(sx);
    float4* __restrict__ out = reinterpret_cast<float4*>(spk_out + (size_t)b * HID + h0);

    float m0 = 0.0f, m1 = 0.0f, m2 = 0.0f, m3 = 0.0f;

    // ---- main scan: t in [0, 990) ----
    #pragma unroll 2
    for (int t = 0; t < T_MAIN; ++t) {
        const float4 xv = sx4[t];
        const float c0 = fmaf(xv.z, wA2, fmaf(xv.y, wA1, xv.x * wA0));
        const float c1 = fmaf(xv.z, wB2, fmaf(xv.y, wB1, xv.x * wB0));
        const float c2 = fmaf(xv.z, wC2, fmaf(xv.y, wC1, xv.x * wC0));
        const float c3 = fmaf(xv.z, wD2, fmaf(xv.y, wD1, xv.x * wD0));
        // exact reference: mem_new = (beta*mem + cur) * (1 - (mem_prev > 1))
        m0 = (m0 > THRESH) ? 0.0f : fmaf(BETA, m0, c0);
        m1 = (m1 > THRESH) ? 0.0f : fmaf(BETA, m1, c1);
        m2 = (m2 > THRESH) ? 0.0f : fmaf(BETA, m2, c2);
        m3 = (m3 > THRESH) ? 0.0f : fmaf(BETA, m3, c3);
        float4 sp;
        sp.x = (m0 > THRESH) ? 1.0f : 0.0f;
        sp.y = (m1 > THRESH) ? 1.0f : 0.0f;
        sp.z = (m2 > THRESH) ? 1.0f : 0.0f;
        sp.w = (m3 > THRESH) ? 1.0f : 0.0f;
        __stcs(out + (size_t)t * (BH / 4), sp);   // streaming STG.128
    }

    // ---- tail: t in [990, 1000), store spikes + accumulate readout ----
    const float4 w2o0 = reinterpret_cast<const float4*>(W2 + h0)[0];
    const float4 w2o1 = reinterpret_cast<const float4*>(W2 + HID + h0)[0];
    float acc[20];

    #pragma unroll
    for (int k = 0; k < 10; ++k) {
        const int t = T_MAIN + k;
        const float4 xv = sx4[t];
        const float c0 = fmaf(xv.z, wA2, fmaf(xv.y, wA1, xv.x * wA0));
        const float c1 = fmaf(xv.z, wB2, fmaf(xv.y, wB1, xv.x * wB0));
        const float c2 = fmaf(xv.z, wC2, fmaf(xv.y, wC1, xv.x * wC0));
        const float c3 = fmaf(xv.z, wD2, fmaf(xv.y, wD1, xv.x * wD0));
        m0 = (m0 > THRESH) ? 0.0f : fmaf(BETA, m0, c0);
        m1 = (m1 > THRESH) ? 0.0f : fmaf(BETA, m1, c1);
        m2 = (m2 > THRESH) ? 0.0f : fmaf(BETA, m2, c2);
        m3 = (m3 > THRESH) ? 0.0f : fmaf(BETA, m3, c3);
        float4 sp;
        sp.x = (m0 > THRESH) ? 1.0f : 0.0f;
        sp.y = (m1 > THRESH) ? 1.0f : 0.0f;
        sp.z = (m2 > THRESH) ? 1.0f : 0.0f;
        sp.w = (m3 > THRESH) ? 1.0f : 0.0f;
        __stcs(out + (size_t)t * (BH / 4), sp);

        float q0 = sp.x * w2o0.x; q0 = fmaf(sp.y, w2o0.y, q0);
        q0 = fmaf(sp.z, w2o0.z, q0); q0 = fmaf(sp.w, w2o0.w, q0);
        float q1 = sp.x * w2o1.x; q1 = fmaf(sp.y, w2o1.y, q1);
        q1 = fmaf(sp.z, w2o1.z, q1); q1 = fmaf(sp.w, w2o1.w, q1);
        acc[2 * k + 0] = q0;
        acc[2 * k + 1] = q1;
    }

    // ---- block reduction of the 20 partials ----
    #pragma unroll
    for (int j = 0; j < 20; ++j) {
        #pragma unroll
        for (int off = 16; off > 0; off >>= 1)
            acc[j] += __shfl_xor_sync(0xFFFFFFFFu, acc[j], off);
    }
    if (lane == 0) {
        #pragma unroll
        for (int j = 0; j < 20; ++j) red[wid][j] = acc[j];
    }
    __syncthreads();

    if (tid < 20)
        tot[tid] = red[0][tid] + red[1][tid] + red[2][tid] + red[3][tid];
    __syncthreads();

    if (tid < NOUT) {
        float s = 0.0f;
        #pragma unroll
        for (int k = 0; k < 10; ++k) {
            const float z = tot[2 * k + tid];
            s += 1.0f / (1.0f + expf(-z));
        }
        avg_out[b * NOUT + tid] = s * 0.1f;
    }
}

// ---------------------------------------------------------------------------
extern "C" void kernel_launch(void* const* d_in, const int* in_sizes, int n_in,
                              void* d_out, int out_size)
{
    const float* x  = (const float*)d_in[0];   // [1000, 256, 3]
    const float* W1 = (const float*)d_in[1];   // [512, 3]
    const float* W2 = (const float*)d_in[2];   // [2, 512]
    float* out = (float*)d_out;

    float* spk_out = out;                      // 131,072,000 floats
    float* avg_out = out + SPK_ELEMS;          // 512 floats

    snn_fused_kernel<<<BATCH, 128>>>(x, W1, W2, spk_out, avg_out);
}

// round 17
// speedup vs baseline: 1.2137x; 1.1361x over previous
#include <cuda_runtime.h>
#include <cuda_bf16.h>

// Problem constants
#define T_STEPS 1000
#define T_MAIN  990            // readout tail covers [990, 1000)
#define BATCH   256
#define HID     512
#define NIN     3
#define NOUT    2
#define BH      (BATCH * HID)             // 131072
#define SPK_ELEMS ((size_t)T_STEPS * BH)  // 131,072,000

#define BETA    0.8f
#define THRESH  1.0f

// ---------------------------------------------------------------------------
// b-pair fused kernel: 4KB contiguous write bursts.
// Grid: 128 blocks; block owns batch elements b0 = 2*blockIdx.x and b0+1.
// 256 threads: tid < 128 -> b0, tid >= 128 -> b1; each thread owns 4
// consecutive hidden units of its b (STG.128). Since (b, h) is contiguous in
// a t-slice, the block's 256 stores per timestep cover ONE contiguous 4KB
// region [b0*2KB, b0*2KB + 4KB) -> double the HBM burst length per row
// activation vs the 2KB-per-block champion.
// x for both b's staged in shared (2 x 16KB, float4-padded rows).
// Readout tail fused; per-b block reduction (warps 0-3 = b0, 4-7 = b1).
// ---------------------------------------------------------------------------
__global__ __launch_bounds__(256)
void snn_fused_kernel(const float* __restrict__ x,     // [T, B, 3]
                      const float* __restrict__ W1,    // [512, 3]
                      const float* __restrict__ W2,    // [2, 512]
                      float* __restrict__ spk_out,     // [T, B, 512]
                      float* __restrict__ avg_out)     // [B, 2]
{
    __shared__ float sx[2][T_STEPS * 4];   // 32 KB, x rows padded 3 -> 4
    __shared__ float red[8][20];
    __shared__ float tot[2][20];

    const int tid   = threadIdx.x;
    const int lane  = tid & 31;
    const int wid   = tid >> 5;            // 0..7
    const int sub   = tid >> 7;            // 0 -> b0, 1 -> b1
    const int ltid  = tid & 127;           // thread index within its b
    const int b     = blockIdx.x * 2 + sub;
    const int h0    = ltid * 4;

    // Stage x[:, b, :] into this half's shared bank (3000 loads / 128 threads)
    for (int idx = ltid; idx < T_STEPS * NIN; idx += 128) {
        const int t = idx / 3;
        const int i = idx - t * 3;
        sx[sub][t * 4 + i] = x[(size_t)t * (BATCH * NIN) + b * NIN + i];
    }
    __syncthreads();

    // W1 rows for the 4 owned hidden units: 12 contiguous floats, 16B aligned
    const float4 w1a = reinterpret_cast<const float4*>(W1 + h0 * 3)[0];
    const float4 w1b = reinterpret_cast<const float4*>(W1 + h0 * 3)[1];
    const float4 w1c = reinterpret_cast<const float4*>(W1 + h0 * 3)[2];
    const float wA0 = w1a.x, wA1 = w1a.y, wA2 = w1a.z;
    const float wB0 = w1a.w, wB1 = w1b.x, wB2 = w1b.y;
    const float wC0 = w1b.z, wC1 = w1b.w, wC2 = w1c.x;
    const float wD0 = w1c.y, wD1 = w1c.z, wD2 = w1c.w;

    const float4* __restrict__ sx4 = reinterpret_cast<const float4*>(sx[sub]);
    float4* __restrict__ out = reinterpret_cast<float4*>(spk_out + (size_t)b * HID + h0);

    float m0 = 0.0f, m1 = 0.0f, m2 = 0.0f, m3 = 0.0f;

    // ---- main scan: t in [0, 990) ----
    #pragma unroll 2
    for (int t = 0; t < T_MAIN; ++t) {
        const float4 xv = sx4[t];
        const float c0 = fmaf(xv.z, wA2, fmaf(xv.y, wA1, xv.x * wA0));
        const float c1 = fmaf(xv.z, wB2, fmaf(xv.y, wB1, xv.x * wB0));
        const float c2 = fmaf(xv.z, wC2, fmaf(xv.y, wC1, xv.x * wC0));
        const float c3 = fmaf(xv.z, wD2, fmaf(xv.y, wD1, xv.x * wD0));
        // exact reference: mem_new = (beta*mem + cur) * (1 - (mem_prev > 1))
        m0 = (m0 > THRESH) ? 0.0f : fmaf(BETA, m0, c0);
        m1 = (m1 > THRESH) ? 0.0f : fmaf(BETA, m1, c1);
        m2 = (m2 > THRESH) ? 0.0f : fmaf(BETA, m2, c2);
        m3 = (m3 > THRESH) ? 0.0f : fmaf(BETA, m3, c3);
        float4 sp;
        sp.x = (m0 > THRESH) ? 1.0f : 0.0f;
        sp.y = (m1 > THRESH) ? 1.0f : 0.0f;
        sp.z = (m2 > THRESH) ? 1.0f : 0.0f;
        sp.w = (m3 > THRESH) ? 1.0f : 0.0f;
        __stcs(out + (size_t)t * (BH / 4), sp);   // streaming STG.128
    }

    // ---- tail: t in [990, 1000), store spikes + accumulate readout ----
    const float4 w2o0 = reinterpret_cast<const float4*>(W2 + h0)[0];
    const float4 w2o1 = reinterpret_cast<const float4*>(W2 + HID + h0)[0];
    float acc[20];

    #pragma unroll
    for (int k = 0; k < 10; ++k) {
        const int t = T_MAIN + k;
        const float4 xv = sx4[t];
        const float c0 = fmaf(xv.z, wA2, fmaf(xv.y, wA1, xv.x * wA0));
        const float c1 = fmaf(xv.z, wB2, fmaf(xv.y, wB1, xv.x * wB0));
        const float c2 = fmaf(xv.z, wC2, fmaf(xv.y, wC1, xv.x * wC0));
        const float c3 = fmaf(xv.z, wD2, fmaf(xv.y, wD1, xv.x * wD0));
        m0 = (m0 > THRESH) ? 0.0f : fmaf(BETA, m0, c0);
        m1 = (m1 > THRESH) ? 0.0f : fmaf(BETA, m1, c1);
        m2 = (m2 > THRESH) ? 0.0f : fmaf(BETA, m2, c2);
        m3 = (m3 > THRESH) ? 0.0f : fmaf(BETA, m3, c3);
        float4 sp;
        sp.x = (m0 > THRESH) ? 1.0f : 0.0f;
        sp.y = (m1 > THRESH) ? 1.0f : 0.0f;
        sp.z = (m2 > THRESH) ? 1.0f : 0.0f;
        sp.w = (m3 > THRESH) ? 1.0f : 0.0f;
        __stcs(out + (size_t)t * (BH / 4), sp);

        float q0 = sp.x * w2o0.x; q0 = fmaf(sp.y, w2o0.y, q0);
        q0 = fmaf(sp.z, w2o0.z, q0); q0 = fmaf(sp.w, w2o0.w, q0);
        float q1 = sp.x * w2o1.x; q1 = fmaf(sp.y, w2o1.y, q1);
        q1 = fmaf(sp.z, w2o1.z, q1); q1 = fmaf(sp.w, w2o1.w, q1);
        acc[2 * k + 0] = q0;
        acc[2 * k + 1] = q1;
    }

    // ---- per-b block reduction of the 20 partials ----
    // warps 0-3 hold b0's threads, warps 4-7 hold b1's.
    #pragma unroll
    for (int j = 0; j < 20; ++j) {
        #pragma unroll
        for (int off = 16; off > 0; off >>= 1)
            acc[j] += __shfl_xor_sync(0xFFFFFFFFu, acc[j], off);
    }
    if (lane == 0) {
        #pragma unroll
        for (int j = 0; j < 20; ++j) red[wid][j] = acc[j];
    }
    __syncthreads();

    if (tid < 40) {                     // tid = sub2*20 + j
        const int s2 = tid / 20;        // which b
        const int j  = tid - s2 * 20;
        tot[s2][j] = red[s2 * 4 + 0][j] + red[s2 * 4 + 1][j]
                   + red[s2 * 4 + 2][j] + red[s2 * 4 + 3][j];
    }
    __syncthreads();

    if (tid < 2 * NOUT) {               // tid = s2*2 + o
        const int s2 = tid >> 1;
        const int o  = tid & 1;
        float s = 0.0f;
        #pragma unroll
        for (int k = 0; k < 10; ++k) {
            const float z = tot[s2][2 * k + o];
            s += 1.0f / (1.0f + expf(-z));
        }
        avg_out[(blockIdx.x * 2 + s2) * NOUT + o] = s * 0.1f;
    }
}

// ---------------------------------------------------------------------------
extern "C" void kernel_launch(void* const* d_in, const int* in_sizes, int n_in,
                              void* d_out, int out_size)
{
    const float* x  = (const float*)d_in[0];   // [1000, 256, 3]
    const float* W1 = (const float*)d_in[1];   // [512, 3]
    const float* W2 = (const float*)d_in[2];   // [2, 512]
    float* out = (float*)d_out;

    float* spk_out = out;                      // 131,072,000 floats
    float* avg_out = out + SPK_ELEMS;          // 512 floats

    snn_fused_kernel<<<BATCH / 2, 256>>>(x, W1, W2, spk_out, avg_out);
}